// round 17
// baseline (speedup 1.0000x reference)
#include <cuda_runtime.h>
#include <cuda_fp16.h>
#include <math.h>

#define Bq 4
#define Lq 4096
#define Hq 256
#define NHq 8
#define Tq 64
#define Dq 32
#define WINq 16
#define NEG_SLOPE 5.0f
#define MASK_FILL -1e12f

// ---------------- scratch (device globals; no allocation allowed) ----------------
__device__ float g_types_h[Bq * Tq * Hq];
__device__ float g_ch[Bq * Lq * Hq];
__device__ float g_U[Bq * Lq * Hq];
__device__ float g_uq[Bq * NHq * Lq];
__device__ float g_ds[Bq * NHq * Lq];
__device__ float g_dt[Bq * NHq * Tq];
__device__ unsigned g_WtF16[3 * 256 * 128];   // transposed f16x2 weights [w][n][kpair]

__device__ __forceinline__ float leaky(float x) { return x >= 0.f ? x : NEG_SLOPE * x; }

__device__ __forceinline__ unsigned pack_f16x2(float lo_elem, float hi_elem) {
    unsigned r;
    asm("cvt.rn.f16x2.f32 %0, %1, %2;" : "=r"(r) : "f"(hi_elem), "f"(lo_elem));
    return r;
}

__device__ __forceinline__ void mma16f(float c[4], const unsigned a[4], const unsigned b[2]) {
    asm volatile(
        "mma.sync.aligned.m16n8k16.row.col.f32.f16.f16.f32 "
        "{%0,%1,%2,%3}, {%4,%5,%6,%7}, {%8,%9}, {%0,%1,%2,%3};"
        : "+f"(c[0]), "+f"(c[1]), "+f"(c[2]), "+f"(c[3])
        : "r"(a[0]), "r"(a[1]), "r"(a[2]), "r"(a[3]), "r"(b[0]), "r"(b[1]));
}

// ---- ldmatrix-based fragment loads (rows 16B-aligned: strides 20/36/44 uints) ----
__device__ __forceinline__ void gatherA16(const unsigned* U, int stride,
                                          int R0, int KP0, int lane, unsigned a[4]) {
    int grp = lane >> 3, lr = lane & 7;
    int row = R0 + lr + ((grp & 1) << 3);
    int kp  = KP0 + ((grp >> 1) << 2);
    unsigned addr = (unsigned)__cvta_generic_to_shared(U + row * stride + kp);
    asm volatile("ldmatrix.sync.aligned.m8n8.x4.shared.b16 {%0,%1,%2,%3}, [%4];"
                 : "=r"(a[0]), "=r"(a[1]), "=r"(a[2]), "=r"(a[3]) : "r"(addr));
}
__device__ __forceinline__ void gatherB16(const unsigned* U, int stride,
                                          int N0, int KP0, int lane, unsigned bb[2]) {
    int grp = (lane >> 3) & 1, lr = lane & 7;
    int row = N0 + lr;
    int kp  = KP0 + (grp << 2);
    unsigned addr = (unsigned)__cvta_generic_to_shared(U + row * stride + kp);
    asm volatile("ldmatrix.sync.aligned.m8n8.x2.shared.b16 {%0,%1}, [%2];"
                 : "=r"(bb[0]), "=r"(bb[1]) : "r"(addr));
}
// transposed B-fragment load from row-major [k][n] halves array.
// N0, K0h in half units (N0 multiple of 8 -> 16B aligned rows).
__device__ __forceinline__ void gatherB16t(const unsigned* U, int stride,
                                           int N0, int K0h, int lane, unsigned bb[2]) {
    int lr = lane & 15;
    unsigned addr = (unsigned)__cvta_generic_to_shared(
        (const unsigned short*)U + (size_t)(K0h + lr) * (stride * 2) + N0);
    asm volatile("ldmatrix.sync.aligned.m8n8.x2.trans.shared.b16 {%0,%1}, [%2];"
                 : "=r"(bb[0]), "=r"(bb[1]) : "r"(addr));
}

__device__ __forceinline__ int mask_mode(const void* m) {
    unsigned u = *(const unsigned*)m;
    if (u == 0x01010101u) return 0;
    if (u == 0x3F800000u) return 2;
    return 1;
}
__device__ __forceinline__ bool mask_at(const void* m, int mode, long idx) {
    if (mode == 0) return ((const unsigned char*)m)[idx] != 0;
    if (mode == 1) return ((const int*)m)[idx] != 0;
    return ((const float*)m)[idx] != 0.f;
}

// ---------------- prep: transpose + f16-pack the three 256x256 weights ---------
__global__ __launch_bounds__(256) void prep_weights(
    const float* __restrict__ W0, const float* __restrict__ W1,
    const float* __restrict__ W2)
{
    __shared__ float s[32][33];
    const int w = blockIdx.z;
    const float* W = (w == 0) ? W0 : (w == 1) ? W1 : W2;
    const int k0 = blockIdx.x * 32, n0 = blockIdx.y * 32;
    const int tid = threadIdx.x;
#pragma unroll
    for (int it = 0; it < 4; it++) {
        int idx = it * 256 + tid;
        int kr = idx >> 5, nc = idx & 31;
        s[kr][nc] = W[(size_t)(k0 + kr) * 256 + n0 + nc];
    }
    __syncthreads();
#pragma unroll
    for (int it = 0; it < 2; it++) {
        int idx = it * 256 + tid;
        int nn = idx >> 4, kp = idx & 15;
        size_t o = (size_t)(w * 256 + n0 + nn) * 128 + (k0 >> 1) + kp;
        g_WtF16[o] = pack_f16x2(s[2 * kp][nn], s[2 * kp + 1][nn]);
    }
}

// ---------------- fp16 GEMM + fused row-dot epilogue ----------------------------
__global__ __launch_bounds__(256) void gemm_f16(
    const float* __restrict__ A, int wsel,
    const float* __restrict__ bias, float* __restrict__ C,
    int dotanh, int mode,
    const float* __restrict__ upon, const float* __restrict__ down)
{
    __shared__ unsigned sA[128 * 20];
    __shared__ unsigned sB[64 * 20];

    const int tid = threadIdx.x;
    const int wid = tid >> 5, lane = tid & 31;
    const int wm = wid >> 1, wn = wid & 1;
    const int bm = blockIdx.y * 128;
    const int bn = blockIdx.x * 64;
    const unsigned* WF = g_WtF16 + (size_t)wsel * 256 * 128;

    float acc[2][4][4];
#pragma unroll
    for (int mt = 0; mt < 2; mt++)
#pragma unroll
        for (int nt = 0; nt < 4; nt++)
#pragma unroll
            for (int r = 0; r < 4; r++) acc[mt][nt][r] = 0.f;

    for (int chunk = 0; chunk < 8; chunk++) {
        const int kc0 = chunk * 32;
#pragma unroll
        for (int i = 0; i < 4; i++) {
            int fidx = i * 256 + tid;
            int row = fidx >> 3, col4 = fidx & 7;
            float4 v = *(const float4*)(A + (size_t)(bm + row) * 256 + kc0 + col4 * 4);
            int o = row * 20 + col4 * 2;
            *(uint2*)&sA[o] = make_uint2(pack_f16x2(v.x, v.y), pack_f16x2(v.z, v.w));
        }
#pragma unroll
        for (int i = 0; i < 2; i++) {
            int fidx = i * 256 + tid;
            int row = fidx >> 3, j = fidx & 7;
            size_t src = (size_t)(bn + row) * 128 + (kc0 >> 1) + j * 2;
            *(uint2*)&sB[row * 20 + j * 2] = *(const uint2*)&WF[src];
        }
        __syncthreads();
#pragma unroll
        for (int k16 = 0; k16 < 2; k16++) {
            unsigned a[2][4];
#pragma unroll
            for (int mt = 0; mt < 2; mt++)
                gatherA16(sA, 20, wm * 32 + mt * 16, k16 * 8, lane, a[mt]);
#pragma unroll
            for (int nt = 0; nt < 4; nt++) {
                unsigned bb[2];
                gatherB16(sB, 20, wn * 32 + nt * 8, k16 * 8, lane, bb);
#pragma unroll
                for (int mt = 0; mt < 2; mt++) mma16f(acc[mt][nt], a[mt], bb);
            }
        }
        __syncthreads();
    }

    const int row0 = bm + wm * 32 + (lane >> 2);
    const int col0 = bn + wn * 32 + (lane & 3) * 2;
    float pa[4] = {0.f, 0.f, 0.f, 0.f};
    float pd[4] = {0.f, 0.f, 0.f, 0.f};
#pragma unroll
    for (int mt = 0; mt < 2; mt++)
#pragma unroll
        for (int nt = 0; nt < 4; nt++) {
            int r = row0 + mt * 16;
            int c = col0 + nt * 8;
            float b0 = bias[c], b1 = bias[c + 1];
            float v00 = acc[mt][nt][0] + b0, v01 = acc[mt][nt][1] + b1;
            float v10 = acc[mt][nt][2] + b0, v11 = acc[mt][nt][3] + b1;
            if (mode == 1) {
                float u0 = upon[c], u1 = upon[c + 1];
                float d0 = down[c], d1 = down[c + 1];
                pa[mt * 2 + 0] += v00 * u0 + v01 * u1;
                pa[mt * 2 + 1] += v10 * u0 + v11 * u1;
                pd[mt * 2 + 0] += v00 * d0 + v01 * d1;
                pd[mt * 2 + 1] += v10 * d0 + v11 * d1;
            } else if (mode == 2) {
                float d0 = down[c], d1 = down[c + 1];
                pd[mt * 2 + 0] += v00 * d0 + v01 * d1;
                pd[mt * 2 + 1] += v10 * d0 + v11 * d1;
            }
            float2 o0 = make_float2(v00, v01);
            float2 o1 = make_float2(v10, v11);
            if (dotanh) {
                o0.x = tanhf(o0.x); o0.y = tanhf(o0.y);
                o1.x = tanhf(o1.x); o1.y = tanhf(o1.y);
            }
            *(float2*)(C + (size_t)r * 256 + c)       = o0;
            *(float2*)(C + (size_t)(r + 8) * 256 + c) = o1;
        }

    if (mode) {
#pragma unroll
        for (int j = 0; j < 4; j++) {
            pa[j] += __shfl_xor_sync(0xFFFFFFFFu, pa[j], 1);
            pa[j] += __shfl_xor_sync(0xFFFFFFFFu, pa[j], 2);
            pd[j] += __shfl_xor_sync(0xFFFFFFFFu, pd[j], 1);
            pd[j] += __shfl_xor_sync(0xFFFFFFFFu, pd[j], 2);
        }
        if ((lane & 3) == 0) {
            const int hn = (bn >> 5) + wn;
#pragma unroll
            for (int j = 0; j < 4; j++) {
                int row = row0 + (j >> 1) * 16 + (j & 1) * 8;
                if (mode == 1) {
                    int b = row >> 12, l = row & 4095;
                    g_uq[((size_t)(b * NHq + hn)) * Lq + l] = pa[j];
                    g_ds[((size_t)(b * NHq + hn)) * Lq + l] = pd[j];
                } else {
                    int b = row >> 6, t = row & 63;
                    g_dt[(b * NHq + hn) * Tq + t] = pd[j];
                }
            }
        }
    }
}

// ---------------- attention core v8: fp16, ldmatrix.trans, no transpose phase ---
#define OFF_XT    0        // crossT 32 x 20
#define OFF_CHa   640      // CH 80 x 20
#define OFF_TY    2240     // types 64 x 20
#define OFF_CQ    3520     // CQ 64 x 20
#define OFF_WT    4800     // Wt 64 x 36
#define OFF_WW    7104     // Wwin 64 x 44
#define OFF_LT    9920     // logitsT float [64][68]
#define OFF_G     14272    // band G float [64][21]
#define OFF_UQ    15616
#define OFF_DS    15696
#define OFF_MK    15776
#define OFF_DT    15856
#define SMEM_UINTS 15920
#define ATTN_SMEM_BYTES (SMEM_UINTS * 4)

__global__ __launch_bounds__(512, 3) void attn_f16_kernel(
    const float* __restrict__ cross, const void* __restrict__ maskp,
    const float* __restrict__ context)
{
    extern __shared__ unsigned SU[];
    float* SF = (float*)SU;
    __half* SH = (__half*)SU;
    const int tid = threadIdx.x, wid = tid >> 5, lane = tid & 31;
    const int n = blockIdx.y, b = blockIdx.z;
    const int l0 = blockIdx.x * 64;
    const int mmode = mask_mode(maskp);
    const int bnL = (b * NHq + n) * Lq;
    const long maskbase = (long)b * Lq;

    // ---------------- stage row-major (packed f16x2 stores) + zero Wwin --------
    {
        const int j2 = lane & 15, rs = lane >> 4;
#pragma unroll
        for (int it = 0; it < 2; it++) {
            int t = it * 32 + wid * 2 + rs;
            float2 v = *(const float2*)(g_types_h + (size_t)(b * Tq + t) * Hq + n * 32 + 2 * j2);
            SU[OFF_TY + t * 20 + j2] = pack_f16x2(v.x, v.y);
        }
        for (int r = wid * 2 + rs; r < 80; r += 32) {
            int row = l0 + r; if (row > Lq - 1) row = Lq - 1;
            float2 v = *(const float2*)(g_ch + (size_t)(b * Lq + row) * Hq + n * 32 + 2 * j2);
            SU[OFF_CHa + r * 20 + j2] = pack_f16x2(v.x, v.y);
        }
    }
    for (int d = wid; d < 32; d += 16) {
        float v = cross[(size_t)(n * Dq + d) * Dq + lane];
        SH[(OFF_XT << 1) + lane * 40 + d] = __float2half_rn(v);
    }
    {
        uint4 z = make_uint4(0, 0, 0, 0);
        for (int i = tid; i < 704; i += 512) ((uint4*)(SU + OFF_WW))[i] = z;
    }
    for (int i = tid; i < 80; i += 512) {
        int ru = l0 + i; if (ru > Lq - 1) ru = Lq - 1;
        SF[OFF_UQ + i] = g_uq[bnL + ru];
        SF[OFF_MK + i] = mask_at(maskp, mmode, maskbase + ru) ? 1.f : 0.f;
        int rd = l0 + i - 16; if (rd < 0) rd = 0;
        SF[OFF_DS + i] = g_ds[bnL + rd];
    }
    for (int i = tid; i < 64; i += 512) SF[OFF_DT + i] = g_dt[(b * NHq + n) * Tq + i];
    __syncthreads();

    // ---------------- phase A: CQ(64x32) = CH @ crossT (16 warps) ----------------
    {
        const int mt = wid >> 2, nh = wid & 3;
        float acc[4] = {0, 0, 0, 0};
#pragma unroll
        for (int k16 = 0; k16 < 2; k16++) {
            unsigned a[4], bb[2];
            gatherA16(SU + OFF_CHa, 20, mt * 16, k16 * 8, lane, a);
            gatherB16(SU + OFF_XT, 20, nh * 8, k16 * 8, lane, bb);
            mma16f(acc, a, bb);
        }
        const int rlo = mt * 16 + (lane >> 2);
        const int cp = nh * 4 + (lane & 3);
        SU[OFF_CQ + rlo * 20 + cp]       = pack_f16x2(acc[0], acc[1]);
        SU[OFF_CQ + (rlo + 8) * 20 + cp] = pack_f16x2(acc[2], acc[3]);
    }
    __syncthreads();

    // ---------------- phase B ----------------
    if (wid < 8) {     // logitsT
        const int mt = wid >> 1, half = wid & 1;
        float acc2[4][4];
#pragma unroll
        for (int i = 0; i < 4; i++)
#pragma unroll
            for (int r = 0; r < 4; r++) acc2[i][r] = 0.f;
#pragma unroll
        for (int k16 = 0; k16 < 2; k16++) {
            unsigned a[4];
            gatherA16(SU + OFF_CQ, 20, mt * 16, k16 * 8, lane, a);
#pragma unroll
            for (int j = 0; j < 4; j++) {
                unsigned bb[2];
                gatherB16(SU + OFF_TY, 20, (half * 4 + j) * 8, k16 * 8, lane, bb);
                mma16f(acc2[j], a, bb);
            }
        }
        const int rlo = mt * 16 + (lane >> 2);
#pragma unroll
        for (int j = 0; j < 4; j++) {
            int c0 = (half * 4 + j) * 8 + 2 * (lane & 3);
            *(float2*)&SF[OFF_LT + rlo * 68 + c0]       = make_float2(acc2[j][0], acc2[j][1]);
            *(float2*)&SF[OFF_LT + (rlo + 8) * 68 + c0] = make_float2(acc2[j][2], acc2[j][3]);
        }
    } else {           // band G
        const int w = wid - 8;
        const int rb = w >> 1, half = w & 1;
        float accg[2][4];
#pragma unroll
        for (int i = 0; i < 2; i++)
#pragma unroll
            for (int r = 0; r < 4; r++) accg[i][r] = 0.f;
#pragma unroll
        for (int k16 = 0; k16 < 2; k16++) {
            unsigned a[4];
            gatherA16(SU + OFF_CQ, 20, rb * 16, k16 * 8, lane, a);
#pragma unroll
            for (int j = 0; j < 2; j++) {
                unsigned bb[2];
                gatherB16(SU + OFF_CHa, 20, rb * 16 + (half * 2 + j) * 8, k16 * 8, lane, bb);
                mma16f(accg[j], a, bb);
            }
        }
        const int rlo = rb * 16 + (lane >> 2), rhi = rlo + 8;
#pragma unroll
        for (int j = 0; j < 2; j++) {
            int m0 = rb * 16 + (half * 2 + j) * 8 + 2 * (lane & 3);
            int k;
            k = m0 - rlo;     if (k >= 0 && k <= 16) SF[OFF_G + rlo * 21 + k] = accg[j][0];
            k = m0 + 1 - rlo; if (k >= 0 && k <= 16) SF[OFF_G + rlo * 21 + k] = accg[j][1];
            k = m0 - rhi;     if (k >= 0 && k <= 16) SF[OFF_G + rhi * 21 + k] = accg[j][2];
            k = m0 + 1 - rhi; if (k >= 0 && k <= 16) SF[OFF_G + rhi * 21 + k] = accg[j][3];
        }
    }
    __syncthreads();

    // ---------------- softmax (4 rows per warp) ----------------
    for (int i = 0; i < 4; i++) {
        const int r = wid * 4 + i;
        const int l = l0 + r;
        const float uq_l = SF[OFF_UQ + r];

        float lt0 = leaky(uq_l + SF[OFF_DT + lane]      + SF[OFF_LT + r * 68 + lane]);
        float lt1 = leaky(uq_l + SF[OFF_DT + lane + 32] + SF[OFF_LT + r * 68 + 32 + lane]);

        const int ku = (lane <= 16) ? 0 : lane - 16;
        const int kd = (lane < 16) ? lane - 16 : 0;
        const bool ok = (l + kd >= 0) && (l + ku < Lq);
        const bool mk = ok && (SF[OFF_MK + r + ku] != 0.f);
        float lg = leaky(SF[OFF_UQ + r + ku] + SF[OFF_DS + r + kd + 16] + SF[OFF_G + r * 21 + ku]);
        float lw = mk ? lg : MASK_FILL;

        float lw2 = -INFINITY;
        if (lane == 0) {
            const bool ok2 = (l + 16 < Lq);
            const bool mk2 = ok2 && (SF[OFF_MK + r + 16] != 0.f);
            float lg2 = leaky(SF[OFF_UQ + r + 16] + SF[OFF_DS + r + 16] + SF[OFF_G + r * 21 + 16]);
            lw2 = mk2 ? lg2 : MASK_FILL;
        }

        float mx = fmaxf(fmaxf(lt0, lt1), lw);
        if (lane == 0) mx = fmaxf(mx, lw2);
#pragma unroll
        for (int o = 16; o; o >>= 1) mx = fmaxf(mx, __shfl_xor_sync(0xFFFFFFFFu, mx, o));
        float e0 = __expf(lt0 - mx), e1 = __expf(lt1 - mx), ew = __expf(lw - mx);
        float ew2 = (lane == 0) ? __expf(lw2 - mx) : 0.f;
        float sm = e0 + e1 + ew + ew2;
#pragma unroll
        for (int o = 16; o; o >>= 1) sm += __shfl_xor_sync(0xFFFFFFFFu, sm, o);
        const float inv = 1.0f / sm;

        SH[(OFF_WT << 1) + r * 72 + lane]      = __float2half_rn(e0 * inv);
        SH[(OFF_WT << 1) + r * 72 + lane + 32] = __float2half_rn(e1 * inv);

        float wwl = ew * inv;
        float wband = (lane <= 16) ? wwl : 0.f;
#pragma unroll
        for (int o = 16; o; o >>= 1) wband += __shfl_xor_sync(0xFFFFFFFFu, wband, o);
        if (lane == 0) {
            SH[(OFF_WW << 1) + r * 88 + r]      = __float2half_rn(wband);
            SH[(OFF_WW << 1) + r * 88 + r + 16] = __float2half_rn(ew2 * inv);
        } else if (lane >= 17) {
            SH[(OFF_WW << 1) + r * 88 + r + (lane - 16)] = __float2half_rn(wwl);
        }
    }
    __syncthreads();

    // ---------------- update (16 warps; B operands via ldmatrix.trans) ---------
    {
        const int mt = wid & 3;
        const int nth = wid >> 2;
        float acc[4] = {0, 0, 0, 0};
#pragma unroll
        for (int k16 = 0; k16 < 4; k16++) {
            unsigned a[4], bb[2];
            gatherA16(SU + OFF_WT, 36, mt * 16, k16 * 8, lane, a);
            gatherB16t(SU + OFF_TY, 20, nth * 8, k16 * 16, lane, bb);
            mma16f(acc, a, bb);
        }
#pragma unroll
        for (int k16 = 0; k16 < 2; k16++) {   // band: kpairs [mt*8, mt*8+16)
            const int KP0 = mt * 8 + k16 * 8;
            unsigned a[4], bb[2];
            gatherA16(SU + OFF_WW, 44, mt * 16, KP0, lane, a);
            gatherB16t(SU + OFF_CHa, 20, nth * 8, KP0 * 2, lane, bb);
            mma16f(acc, a, bb);
        }
        const int llo = l0 + mt * 16 + (lane >> 2);
        const int col = n * 32 + nth * 8 + 2 * (lane & 3);
        size_t g0 = (size_t)(b * Lq + llo) * Hq + col;
        size_t g1 = (size_t)(b * Lq + llo + 8) * Hq + col;
        float2 c0 = *(const float2*)&context[g0];
        float2 c1 = *(const float2*)&context[g1];
        *(float2*)&g_U[g0] = make_float2(acc[0] + c0.x, acc[1] + c0.y);
        *(float2*)&g_U[g1] = make_float2(acc[2] + c1.x, acc[3] + c1.y);
    }
}

// ---------------- launch ----------------
extern "C" void kernel_launch(void* const* d_in, const int* in_sizes, int n_in,
                              void* d_out, int out_size)
{
    (void)in_sizes; (void)n_in; (void)out_size;
    const float* context   = (const float*)d_in[0];
    const float* types     = (const float*)d_in[1];
    const void*  cmask     = d_in[2];
    const float* W_types   = (const float*)d_in[3];
    const float* b_types   = (const float*)d_in[4];
    const float* W_context = (const float*)d_in[5];
    const float* b_context = (const float*)d_in[6];
    const float* upon      = (const float*)d_in[7];
    const float* down      = (const float*)d_in[8];
    const float* cross     = (const float*)d_in[9];
    const float* W_out     = (const float*)d_in[10];
    const float* b_out     = (const float*)d_in[11];
    float* out = (float*)d_out;

    float *p_types_h, *p_ch, *p_U;
    cudaGetSymbolAddress((void**)&p_types_h, g_types_h);
    cudaGetSymbolAddress((void**)&p_ch, g_ch);
    cudaGetSymbolAddress((void**)&p_U, g_U);

    cudaFuncSetAttribute(attn_f16_kernel,
                         cudaFuncAttributeMaxDynamicSharedMemorySize, ATTN_SMEM_BYTES);

    prep_weights<<<dim3(8, 8, 3), 256>>>(W_types, W_context, W_out);
    gemm_f16<<<dim3(4, 2), 256>>>(types, 0, b_types, p_types_h, 0, 2, upon, down);
    gemm_f16<<<dim3(4, 128), 256>>>(context, 1, b_context, p_ch, 0, 1, upon, down);
    attn_f16_kernel<<<dim3(Lq / 64, NHq, Bq), 512, ATTN_SMEM_BYTES>>>(cross, cmask, context);
    gemm_f16<<<dim3(4, 128), 256>>>(p_U, 2, b_out, out, 1, 0, upon, down);
}